// round 9
// baseline (speedup 1.0000x reference)
#include <cuda_runtime.h>
typedef unsigned long long ull;

constexpr int Bn = 8, Sn = 2048, Pn = 1024, ITERS = 50;
constexpr int CPB = 32, GRID = Bn * CPB, NT = 256;
constexpr int NCX = Sn / 16;                  // 128 X-chunks

constexpr float SQI   = 12.011224081528898f;  // sqrt((1/eps)*log2 e)
constexpr float IL2   = 144.26950408889634f;
constexpr float LOG2S = 11.0f;
constexpr float CL    = 80.f;                 // clamp headroom above R
constexpr float TH    = 30.f;                 // prune threshold (2^-30)

__device__ float g_fs[Bn * Sn], g_gs[Bn * Pn], g_part[GRID];
__device__ unsigned g_cnt[Bn], g_sns[Bn], g_gcnt;

__device__ __forceinline__ float ex2(float x) { float r; asm("ex2.approx.f32 %0, %1;" : "=f"(r) : "f"(x)); return r; }
__device__ __forceinline__ float lg2(float x) { float r; asm("lg2.approx.f32 %0, %1;" : "=f"(r) : "f"(x)); return r; }
__device__ __forceinline__ ull pk(float lo, float hi) { ull r; asm("mov.b64 %0, {%1, %2};" : "=l"(r) : "f"(lo), "f"(hi)); return r; }
__device__ __forceinline__ void upk(ull p, float& a, float& b) { asm("mov.b64 {%0, %1}, %2;" : "=f"(a), "=f"(b) : "l"(p)); }
__device__ __forceinline__ ull add2(ull a, ull b) { ull r; asm("add.rn.f32x2 %0, %1, %2;" : "=l"(r) : "l"(a), "l"(b)); return r; }
__device__ __forceinline__ ull fma2(ull a, ull b, ull c) { ull r; asm("fma.rn.f32x2 %0, %1, %2, %3;" : "=l"(r) : "l"(a), "l"(b), "l"(c)); return r; }
__device__ __forceinline__ float warp_sum(float a) {
    #pragma unroll
    for (int o = 16; o; o >>= 1) a += __shfl_xor_sync(~0u, a, o);
    return a;
}
__device__ __forceinline__ float warp_min(float a) {
    #pragma unroll
    for (int o = 16; o; o >>= 1) a = fminf(a, __shfl_xor_sync(~0u, a, o));
    return a;
}
__device__ __forceinline__ float warp_maxr(float a) {
    #pragma unroll
    for (int o = 16; o; o >>= 1) a = fmaxf(a, __shfl_xor_sync(~0u, a, o));
    return a;
}
__device__ __forceinline__ unsigned fkey(float f) {
    unsigned u = __float_as_uint(f);
    return (u & 0x80000000u) ? ~u : (u | 0x80000000u);
}
__device__ void bitonic(ull* k, int n) {
    for (int sz = 2; sz <= n; sz <<= 1)
        for (int st = sz >> 1; st > 0; st >>= 1) {
            __syncthreads();
            for (int i = threadIdx.x; i < n; i += NT) {
                int j = i ^ st;
                if (j > i) {
                    bool up = ((i & sz) == 0);
                    ull a = k[i], b = k[j];
                    if ((a > b) == up) { k[i] = b; k[j] = a; }
                }
            }
        }
    __syncthreads();
}
__device__ __forceinline__ int lbound(const float* a, int n, float key) {
    int lo = 0, hi = n;
    while (lo < hi) { int mid = (lo + hi) >> 1; if (a[mid] < key) lo = mid + 1; else hi = mid; }
    return lo;
}
// corner max of bilinear product over [u0,u1]x[v0,v1]
__device__ __forceinline__ float cmax4(float u0, float u1, float v0, float v1) {
    return fmaxf(fmaxf(u0 * v0, u0 * v1), fmaxf(u1 * v0, u1 * v1));
}
__device__ __forceinline__ void bat_bar(int b, unsigned& ls) {
    ls ^= 1u;
    __syncthreads();
    if (threadIdx.x == 0) {
        unsigned old;
        asm volatile("atom.acq_rel.gpu.add.u32 %0,[%1],%2;"
                     : "=r"(old) : "l"(&g_cnt[b]), "r"(1u) : "memory");
        if (old == CPB - 1) {
            g_cnt[b] = 0;
            asm volatile("st.release.gpu.u32 [%0],%1;" :: "l"(&g_sns[b]), "r"(ls) : "memory");
        } else {
            unsigned v;
            do { asm volatile("ld.acquire.gpu.u32 %0,[%1];" : "=r"(v) : "l"(&g_sns[b]) : "memory"); }
            while (v != ls);
        }
    }
    __syncthreads();
}
// [lo,hi] chunk range from keep-ballots (contiguous superset of kept set)
__device__ __forceinline__ void rng_from_bb(const unsigned* bb, int nq, int nc, int& lo, int& hi) {
    lo = 0; hi = nc - 1;
    for (int q = nq - 1; q >= 0; q--) if (bb[q]) lo = q * 32 + __ffs(bb[q]) - 1;
    for (int q = 0; q < nq; q++)      if (bb[q]) hi = q * 32 + 31 - __clz(bb[q]);
}

__global__ void __launch_bounds__(NT, 2) sinkhorn_kernel(
    const float* __restrict__ pred, const int* __restrict__ labels,
    const float* __restrict__ pos, float* __restrict__ out)
{
    __shared__ __align__(16) float X1[Sn], X2[Sn], Qx[Sn];
    __shared__ __align__(16) float Y1c[Pn], Y2c[Pn], Qyc[Pn], l2bC[Pn];
    __shared__ float sA[512], sRf[64], sRg[32], sred[8];
    __shared__ float UQy[64], Y1L[64], Y1H[64], A2y[64];
    __shared__ float UQx[NCX], X1L[NCX], X1H[NCX], A2x[NCX];
    __shared__ int swp[8], sPvA[1];

    int tid = threadIdx.x, w = tid >> 5, lane = tid & 31;
    int b = blockIdx.x >> 5, cb = blockIdx.x & 31;
    int row0 = cb * 64;

    const float2* pr2 = (const float2*)pred + b * Sn;
    const float2* po2 = (const float2*)pos + b * Pn;
    const int*    lab = labels + b * Sn;

    // ---- keys + histogram ----
    ull* xk = (ull*)X1;       // spans X1,X2 (16KB)
    ull* yk = (ull*)Y1c;      // spans Y1c,Y2c (8KB)
    int* hist = (int*)Qx;
    for (int i = tid; i < Sn; i += NT) xk[i] = ((ull)fkey(pr2[i].x) << 32) | (unsigned)i;
    for (int i = tid; i < Pn; i += NT) { yk[i] = ((ull)fkey(po2[i].x) << 32) | (unsigned)i; hist[i] = 0; }
    __syncthreads();
    for (int s = tid; s < Sn; s += NT) atomicAdd(&hist[lab[s]], 1);
    bitonic(xk, Sn);          // internal syncs also publish hist
    bitonic(yk, Pn);
    // pull keys to regs before overwriting regions
    ull myx[8], yk4[4];
    #pragma unroll
    for (int t = 0; t < 8; t++) myx[t] = xk[tid + t * NT];
    #pragma unroll
    for (int k = 0; k < 4; k++) yk4[k] = yk[tid * 4 + k];      // consecutive: stable compaction
    // compaction flags + scan
    int c4[4], tsum = 0;
    #pragma unroll
    for (int k = 0; k < 4; k++) { c4[k] = hist[(int)(yk4[k] & 0xFFFFFFFFu)] > 0; tsum += c4[k]; }
    int pre = tsum;
    #pragma unroll
    for (int o = 1; o < 32; o <<= 1) { int v = __shfl_up_sync(~0u, pre, o); if (lane >= o) pre += v; }
    if (lane == 31) swp[w] = pre;
    __syncthreads();
    if (tid == 0) { int r = 0; for (int i = 0; i < 8; i++) { int v = swp[i]; swp[i] = r; r += v; } sPvA[0] = r; }
    __syncthreads();
    int Pv = sPvA[0];
    int off = swp[w] + pre - tsum;
    // write sorted X and compacted sorted Y
    #pragma unroll
    for (int t = 0; t < 8; t++) {
        int i = tid + t * NT, idx = (int)(myx[t] & 0xFFFFFFFFu);
        float2 p = pr2[idx];
        X1[i] = 2.f * SQI * p.x;  X2[i] = 2.f * SQI * p.y;
    }
    #pragma unroll
    for (int k = 0; k < 4; k++) {
        if (c4[k]) {
            int o = (int)(yk4[k] & 0xFFFFFFFFu);
            float2 p = po2[o];
            Y1c[off] = SQI * p.x;  Y2c[off] = SQI * p.y;
            l2bC[off] = lg2((float)hist[o] * (1.f / (float)Sn));
            off++;
        }
    }
    __syncthreads();   // hist (Qx region) now free
    int PvPad = (Pv + 15) & ~15, ncy = PvPad >> 4;
    for (int i = tid; i < Pn; i += NT) {
        if (i < Pv) Qyc[i] = -(Y1c[i] * Y1c[i] + Y2c[i] * Y2c[i]);   // g=0 -> Qy=-yn
        else { Qyc[i] = -1e30f; Y1c[i] = Y1c[Pv - 1]; Y2c[i] = 0.f; l2bC[i] = 0.f; }
    }
    __syncthreads();
    // static chunk meta + initial UQy
    if (tid < 64) {
        if (tid < ncy) {
            float a2 = 0.f, uq = -3e38f;
            #pragma unroll
            for (int j = 0; j < 16; j++) {
                a2 = fmaxf(a2, fabsf(Y2c[tid * 16 + j]));
                uq = fmaxf(uq, Qyc[tid * 16 + j]);
            }
            Y1L[tid] = Y1c[tid * 16]; Y1H[tid] = Y1c[tid * 16 + 15];
            A2y[tid] = a2; UQy[tid] = uq;
        } else { Y1L[tid] = 0.f; Y1H[tid] = 0.f; A2y[tid] = 0.f; UQy[tid] = -3e38f; }
    }
    if (tid < NCX) {
        float a2 = 0.f;
        #pragma unroll
        for (int j = 0; j < 16; j++) a2 = fmaxf(a2, fabsf(X2[tid * 16 + j]));
        X1L[tid] = X1[tid * 16]; X1H[tid] = X1[tid * 16 + 15]; A2x[tid] = a2;
    }
    unsigned ls = g_sns[b];
    __syncthreads();

    // ---- per-lane constants ----
    int fr0 = row0 + lane, fr1 = fr0 + 32;
    float X1a = X1[fr0], X2a = X2[fr0], X1b_ = X1[fr1], X2b_ = X2[fr1];
    ull X1A = pk(X1a, X1a), X2A = pk(X2a, X2a);
    ull X1B = pk(X1b_, X1b_), X2B = pk(X2b_, X2b_);
    int fj0a = min(max(lbound(Y1c, Pv, 0.5f * X1a) - 8, 0), Pv - 16);
    int fj0b = min(max(lbound(Y1c, Pv, 0.5f * X1b_) - 8, 0), Pv - 16);
    float xlo = X1[row0], xhi = X1[row0 + 63];
    float ax2 = warp_maxr(fmaxf(fabsf(X2a), fabsf(X2b_)));

    int cpc = (Pv + CPB - 1) / CPB;
    int myc0 = cb * cpc;
    int myn = min(cpc, max(0, Pv - myc0));
    int gcol = myc0 + ((lane < myn) ? lane : 0);
    float Y1s = Y1c[gcol], Y2s = Y2c[gcol];
    ull Y1p = pk(Y1s, Y1s), Y2p = pk(Y2s, Y2s);
    int gj0 = min(max(lbound(X1, Sn, 2.f * Y1s) - 8, 0), Sn - 16);
    float ylo = Y1c[myc0], yhi = Y1c[myc0 + max(myn - 1, 0)];
    float ay2 = warp_maxr(fabsf(Y2s));

    for (int it = 0; it < ITERS; ++it) {
        // ================= f half =================
        int flo, fhi;
        {
            float La = -3e38f, Lb = -3e38f;
            #pragma unroll
            for (int j = 0; j < 16; j++) {
                La = fmaxf(La, fmaf(X1a, Y1c[fj0a + j], fmaf(X2a, Y2c[fj0a + j], Qyc[fj0a + j])));
                Lb = fmaxf(Lb, fmaf(X1b_, Y1c[fj0b + j], fmaf(X2b_, Y2c[fj0b + j], Qyc[fj0b + j])));
            }
            float thr = warp_min(fminf(La, Lb)) - TH;
            unsigned bb[2];
            #pragma unroll
            for (int q = 0; q < 2; q++) {
                int c = lane + q * 32;
                float ub = UQy[c] + cmax4(xlo, xhi, Y1L[c], Y1H[c]) + A2y[c] * ax2;
                bb[q] = __ballot_sync(~0u, (c < ncy) && (ub >= thr));
            }
            rng_from_bb(bb, 2, ncy, flo, fhi);
        }
        if (it == 0) {   // seed R = exact row max over kept chunks
            float m0 = -3e38f, m1 = -3e38f;
            for (int c = flo + w; c <= fhi; c += 8) {
                const ull* y1 = (const ull*)(Y1c + c * 16);
                const ull* y2 = (const ull*)(Y2c + c * 16);
                const ull* qq = (const ull*)(Qyc + c * 16);
                #pragma unroll
                for (int j = 0; j < 8; j++) {
                    ull t0 = fma2(X1A, y1[j], fma2(X2A, y2[j], qq[j]));
                    ull t1 = fma2(X1B, y1[j], fma2(X2B, y2[j], qq[j]));
                    float a, b2; upk(t0, a, b2); m0 = fmaxf(m0, fmaxf(a, b2));
                    upk(t1, a, b2); m1 = fmaxf(m1, fmaxf(a, b2));
                }
            }
            sA[w * 64 + lane] = m0;  sA[w * 64 + lane + 32] = m1;
            __syncthreads();
            if (tid < 64) {
                float M = -3e38f;
                #pragma unroll
                for (int i = 0; i < 8; i++) M = fmaxf(M, sA[i * 64 + tid]);
                sRf[tid] = M;
            }
            __syncthreads();
        }
        {
            float R0 = sRf[lane], R1 = sRf[lane + 32];
            ull nR0 = pk(-R0, -R0), nR1 = pk(-R1, -R1);
            float a0 = 0.f, a1 = 0.f, a2 = 0.f, a3 = 0.f;
            for (int c = flo + w; c <= fhi; c += 8) {
                const ull* y1 = (const ull*)(Y1c + c * 16);
                const ull* y2 = (const ull*)(Y2c + c * 16);
                const ull* qq = (const ull*)(Qyc + c * 16);
                #pragma unroll
                for (int j = 0; j < 8; j++) {
                    ull ly1 = y1[j], ly2 = y2[j], q = qq[j];
                    ull t0 = add2(fma2(X1A, ly1, fma2(X2A, ly2, q)), nR0);
                    ull t1 = add2(fma2(X1B, ly1, fma2(X2B, ly2, q)), nR1);
                    float ta, tb; upk(t0, ta, tb);
                    a0 += ex2(fminf(ta, CL));
                    a1 += ex2(fminf(tb, CL));
                    upk(t1, ta, tb);
                    a2 += ex2(fminf(ta, CL));
                    a3 += ex2(fminf(tb, CL));
                }
            }
            sA[w * 64 + lane] = a0 + a1;  sA[w * 64 + lane + 32] = a2 + a3;
        }
        __syncthreads();
        if (tid < 64) {
            float A = 0.f;
            #pragma unroll
            for (int i = 0; i < 8; i++) A += sA[i * 64 + tid];
            A = fmaxf(A, 1e-30f);
            float Lse = sRf[tid] + lg2(A);
            sRf[tid] = Lse;
            g_fs[b * Sn + row0 + tid] = -LOG2S - Lse;     // Qx-form
        }
        bat_bar(b, ls);
        for (int i = tid; i < Sn; i += NT) Qx[i] = __ldcg(&g_fs[b * Sn + i]);
        __syncthreads();
        if (tid < NCX) {
            float uq = -3e38f;
            #pragma unroll
            for (int j = 0; j < 16; j++) uq = fmaxf(uq, Qx[tid * 16 + j]);
            UQx[tid] = uq;
        }
        __syncthreads();

        // ================= g half =================
        int glo, ghi;
        {
            float Lg = -3e38f;
            #pragma unroll
            for (int j = 0; j < 16; j++)
                Lg = fmaxf(Lg, fmaf(Y1s, X1[gj0 + j], fmaf(Y2s, X2[gj0 + j], Qx[gj0 + j])));
            float thr = warp_min(Lg) - TH;
            unsigned bb[4];
            #pragma unroll
            for (int q = 0; q < 4; q++) {
                int c = lane + q * 32;
                float ub = UQx[c] + cmax4(ylo, yhi, X1L[c], X1H[c]) + A2x[c] * ay2;
                bb[q] = __ballot_sync(~0u, ub >= thr);
            }
            rng_from_bb(bb, 4, NCX, glo, ghi);
        }
        if (it == 0) {
            float m = -3e38f;
            for (int c = glo + w; c <= ghi; c += 8) {
                const ull* x1 = (const ull*)(X1 + c * 16);
                const ull* x2 = (const ull*)(X2 + c * 16);
                const ull* qq = (const ull*)(Qx + c * 16);
                #pragma unroll
                for (int j = 0; j < 8; j++) {
                    ull t = fma2(Y1p, x1[j], fma2(Y2p, x2[j], qq[j]));
                    float a, b2; upk(t, a, b2);
                    m = fmaxf(m, fmaxf(a, b2));
                }
            }
            sA[w * 64 + lane] = m;
            __syncthreads();
            if (tid < 32) {
                float M = -3e38f;
                #pragma unroll
                for (int i = 0; i < 8; i++) M = fmaxf(M, sA[i * 64 + tid]);
                sRg[tid] = M;
            }
            __syncthreads();
        }
        {
            float Rg = sRg[lane];
            ull nR = pk(-Rg, -Rg);
            float a0 = 0.f, a1 = 0.f;
            for (int c = glo + w; c <= ghi; c += 8) {
                const ull* x1 = (const ull*)(X1 + c * 16);
                const ull* x2 = (const ull*)(X2 + c * 16);
                const ull* qq = (const ull*)(Qx + c * 16);
                #pragma unroll
                for (int j = 0; j < 8; j++) {
                    ull t = add2(fma2(Y1p, x1[j], fma2(Y2p, x2[j], qq[j])), nR);
                    float ta, tb; upk(t, ta, tb);
                    a0 += ex2(fminf(ta, CL));
                    a1 += ex2(fminf(tb, CL));
                }
            }
            sA[w * 64 + lane] = a0 + a1;
        }
        __syncthreads();
        if (tid < 32) {
            float A = 0.f;
            #pragma unroll
            for (int i = 0; i < 8; i++) A += sA[i * 64 + tid];
            A = fmaxf(A, 1e-30f);
            float Lse = sRg[tid] + lg2(A);
            sRg[tid] = Lse;
            if (tid < myn) g_gs[b * Pn + myc0 + tid] = l2bC[myc0 + tid] - Lse;   // Qy-form
        }
        bat_bar(b, ls);
        for (int i = tid; i < Pv; i += NT) Qyc[i] = __ldcg(&g_gs[b * Pn + i]);
        __syncthreads();
        if (tid < ncy) {
            float uq = -3e38f;
            #pragma unroll
            for (int j = 0; j < 16; j++) uq = fmaxf(uq, Qyc[tid * 16 + j]);
            UQy[tid] = uq;
        }
        __syncthreads();
    }

    // ================= final transport distance =================
    {
        float La = -3e38f, Lb = -3e38f;
        #pragma unroll
        for (int j = 0; j < 16; j++) {
            La = fmaxf(La, fmaf(X1a, Y1c[fj0a + j], fmaf(X2a, Y2c[fj0a + j], Qyc[fj0a + j])));
            Lb = fmaxf(Lb, fmaf(X1b_, Y1c[fj0b + j], fmaf(X2b_, Y2c[fj0b + j], Qyc[fj0b + j])));
        }
        float thr = warp_min(fminf(La, Lb)) - TH;
        unsigned bb[2];
        #pragma unroll
        for (int q = 0; q < 2; q++) {
            int c = lane + q * 32;
            float ub = UQy[c] + cmax4(xlo, xhi, Y1L[c], Y1H[c]) + A2y[c] * ax2;
            bb[q] = __ballot_sync(~0u, (c < ncy) && (ub >= thr));
        }
        int flo, fhi; rng_from_bb(bb, 2, ncy, flo, fhi);

        float q0 = Qx[fr0], q1 = Qx[fr1];
        float xna = 0.25f * (X1a * X1a + X2a * X2a);
        float xnb = 0.25f * (X1b_ * X1b_ + X2b_ * X2b_);
        float acc = 0.f;
        for (int c = flo + w; c <= fhi; c += 8) {
            const ull* y1 = (const ull*)(Y1c + c * 16);
            const ull* y2 = (const ull*)(Y2c + c * 16);
            const ull* qq = (const ull*)(Qyc + c * 16);
            #pragma unroll
            for (int j = 0; j < 8; j++) {
                ull ly1 = y1[j], ly2 = y2[j], q = qq[j];
                ull t0 = fma2(X1A, ly1, fma2(X2A, ly2, q));
                ull t1 = fma2(X1B, ly1, fma2(X2B, ly2, q));
                float qa, qb, y1a, y1b, y2a, y2b, t0a, t0b, t1a, t1b;
                upk(q, qa, qb); upk(ly1, y1a, y1b); upk(ly2, y2a, y2b);
                upk(t0, t0a, t0b); upk(t1, t1a, t1b);
                float yna2 = y1a * y1a + y2a * y2a, ynb2 = y1b * y1b + y2b * y2b;
                acc = fmaf(ex2(fminf(t0a + q0, CL)), qa + yna2 + xna - t0a, acc);
                acc = fmaf(ex2(fminf(t0b + q0, CL)), qb + ynb2 + xna - t0b, acc);
                acc = fmaf(ex2(fminf(t1a + q1, CL)), qa + yna2 + xnb - t1a, acc);
                acc = fmaf(ex2(fminf(t1b + q1, CL)), qb + ynb2 + xnb - t1b, acc);
            }
        }
        acc = warp_sum(acc);
        if (lane == 0) sred[w] = acc;
    }
    __syncthreads();
    if (tid == 0) {
        float s = 0.f;
        #pragma unroll
        for (int i = 0; i < 8; i++) s += sred[i];
        g_part[blockIdx.x] = s;
    }

    // ---- grid-wide deterministic reduce ----
    __threadfence();
    __syncthreads();
    if (blockIdx.x == 0) {
        if (tid == 0) {
            atomicAdd(&g_gcnt, 1u);
            while (*((volatile unsigned*)&g_gcnt) < (unsigned)GRID) { }
            __threadfence();
        }
        __syncthreads();
        sA[tid] = __ldcg(&g_part[tid]);
        __syncthreads();
        #pragma unroll
        for (int o = 128; o; o >>= 1) {
            if (tid < o) sA[tid] += sA[tid + o];
            __syncthreads();
        }
        if (tid == 0) {
            out[0] = sA[0] * (1.f / (IL2 * (float)Bn));
            g_gcnt = 0;
        }
    } else {
        if (tid == 0) atomicAdd(&g_gcnt, 1u);
    }
}

extern "C" void kernel_launch(void* const* d_in, const int* in_sizes, int n_in,
                              void* d_out, int out_size) {
    const float* pred   = (const float*)d_in[0];
    const int*   labels = (const int*)d_in[1];
    const float* pos    = (const float*)d_in[2];
    float*       out    = (float*)d_out;

    sinkhorn_kernel<<<GRID, NT>>>(pred, labels, pos, out);
}

// round 10
// speedup vs baseline: 1.2040x; 1.2040x over previous
#include <cuda_runtime.h>
typedef unsigned long long ull;

constexpr int Bn = 8, Sn = 2048, Pn = 1024, ITERS = 50;
constexpr int CPB = 32, GRID = Bn * CPB, NT = 256;

constexpr float SQI   = 12.011224081528898f;   // sqrt((1/eps)*log2 e)
constexpr float IL2   = 144.26950408889634f;
constexpr float LOG2S = 11.0f;
constexpr float CL    = 80.f;                  // clamp headroom above R

__device__ __align__(16) float g_fs[Bn * Sn];
__device__ __align__(16) float g_gs[Bn * Pn];
__device__ float g_part[GRID];
__device__ unsigned g_cnt[Bn];
__device__ unsigned g_sns[Bn];
__device__ unsigned g_gcnt;

__device__ __forceinline__ float ex2(float x) { float r; asm("ex2.approx.f32 %0, %1;" : "=f"(r) : "f"(x)); return r; }
__device__ __forceinline__ float lg2(float x) { float r; asm("lg2.approx.f32 %0, %1;" : "=f"(r) : "f"(x)); return r; }
__device__ __forceinline__ ull pk(float lo, float hi) { ull r; asm("mov.b64 %0, {%1, %2};" : "=l"(r) : "f"(lo), "f"(hi)); return r; }
__device__ __forceinline__ void upk(ull p, float& a, float& b) { asm("mov.b64 {%0, %1}, %2;" : "=f"(a), "=f"(b) : "l"(p)); }
__device__ __forceinline__ ull add2(ull a, ull b) { ull r; asm("add.rn.f32x2 %0, %1, %2;" : "=l"(r) : "l"(a), "l"(b)); return r; }
__device__ __forceinline__ ull fma2(ull a, ull b, ull c) { ull r; asm("fma.rn.f32x2 %0, %1, %2, %3;" : "=l"(r) : "l"(a), "l"(b), "l"(c)); return r; }
__device__ __forceinline__ float warp_sum(float a) {
    #pragma unroll
    for (int o = 16; o; o >>= 1) a += __shfl_xor_sync(0xffffffffu, a, o);
    return a;
}

// per-batch barrier: release arrive + acquire spin (all CTAs co-resident)
__device__ __forceinline__ void bat_bar(int b, unsigned& ls) {
    ls ^= 1u;
    __syncthreads();
    if (threadIdx.x == 0) {
        unsigned old;
        asm volatile("atom.acq_rel.gpu.add.u32 %0,[%1],%2;"
                     : "=r"(old) : "l"(&g_cnt[b]), "r"(1u) : "memory");
        if (old == CPB - 1) {
            g_cnt[b] = 0;
            asm volatile("st.release.gpu.u32 [%0],%1;" :: "l"(&g_sns[b]), "r"(ls) : "memory");
        } else {
            unsigned v;
            do { asm volatile("ld.acquire.gpu.u32 %0,[%1];" : "=r"(v) : "l"(&g_sns[b]) : "memory"); }
            while (v != ls);
        }
    }
    __syncthreads();
}

__global__ void __launch_bounds__(NT, 3) sinkhorn_kernel(
    const float* __restrict__ pred, const int* __restrict__ labels,
    const float* __restrict__ pos, float* __restrict__ out)
{
    __shared__ __align__(16) float X1[Sn], X2[Sn], Qx[Sn];
    __shared__ __align__(16) float Y1c[Pn], Y2c[Pn], Qyc[Pn], l2bC[Pn];
    __shared__ float sA[512], sRf[64], sRg[32], sred[8];
    __shared__ int swp[8], sPvA[1];

    int tid = threadIdx.x, w = tid >> 5, lane = tid & 31;
    int b = blockIdx.x >> 5, cb = blockIdx.x & 31;
    int row0 = cb * 64;

    // ---- stage X (prescaled by 2*SQI) ----
    const float2* pr2 = (const float2*)pred + b * Sn;
    for (int i = tid; i < Sn; i += NT) {
        float2 p = pr2[i];
        X1[i] = 2.f * SQI * p.x;  X2[i] = 2.f * SQI * p.y;
    }
    // ---- histogram (overlay in Qx region) ----
    int* hist = (int*)Qx;
    for (int i = tid; i < Pn; i += NT) hist[i] = 0;
    __syncthreads();
    const int* lab = labels + b * Sn;
    for (int s = tid; s < Sn; s += NT) atomicAdd(&hist[lab[s]], 1);
    __syncthreads();
    // ---- compact nonzero-weight positions (deterministic prefix scan) ----
    int c4[4], tsum = 0;
    #pragma unroll
    for (int k = 0; k < 4; k++) { c4[k] = hist[tid * 4 + k] > 0; tsum += c4[k]; }
    int pre = tsum;
    #pragma unroll
    for (int o = 1; o < 32; o <<= 1) { int v = __shfl_up_sync(~0u, pre, o); if (lane >= o) pre += v; }
    if (lane == 31) swp[w] = pre;
    __syncthreads();
    if (tid == 0) { int r = 0; for (int i = 0; i < 8; i++) { int v = swp[i]; swp[i] = r; r += v; } sPvA[0] = r; }
    __syncthreads();
    int Pv = sPvA[0];
    int off = swp[w] + pre - tsum;
    const float2* po2 = (const float2*)pos + b * Pn;
    #pragma unroll
    for (int k = 0; k < 4; k++) {
        if (c4[k]) {
            int p = tid * 4 + k;
            float2 yy = po2[p];
            Y1c[off] = SQI * yy.x;  Y2c[off] = SQI * yy.y;
            l2bC[off] = lg2((float)hist[p] * (1.f / (float)Sn));
            off++;
        }
    }
    __syncthreads();   // hist done; Qx region free until first restage
    int PvPad = (Pv + 15) & ~15;
    for (int i = tid; i < Pn; i += NT) {
        if (i < Pv) Qyc[i] = -(Y1c[i] * Y1c[i] + Y2c[i] * Y2c[i]);   // G=0 -> Qy=-yn
        else { Qyc[i] = -1e30f; Y1c[i] = 0.f; Y2c[i] = 0.f; l2bC[i] = 0.f; }
    }
    unsigned ls = g_sns[b];
    __syncthreads();

    // per-lane constants
    int fr0 = row0 + lane, fr1 = fr0 + 32;
    float X1a = X1[fr0], X2a = X2[fr0], X1b_ = X1[fr1], X2b_ = X2[fr1];
    ull X1A = pk(X1a, X1a), X2A = pk(X2a, X2a);
    ull X1B = pk(X1b_, X1b_), X2B = pk(X2b_, X2b_);
    int cpc = (Pv + CPB - 1) / CPB;
    int myc0 = cb * cpc;
    int myn = min(cpc, max(0, Pv - myc0));
    int gcol = myc0 + ((lane < myn) ? lane : 0);
    float Y1s = Y1c[gcol], Y2s = Y2c[gcol];
    ull Y1p = pk(Y1s, Y1s), Y2p = pk(Y2s, Y2s);
    int nch = PvPad >> 4;

    for (int it = 0; it < ITERS; ++it) {
        // ================= f half =================
        if (it == 0) {   // seed R: exact row max (fma-only pass)
            float m0 = -3e38f, m1 = -3e38f;
            for (int c = w; c < nch; c += 8) {
                const ull* y1 = (const ull*)(Y1c + c * 16);
                const ull* y2 = (const ull*)(Y2c + c * 16);
                const ull* qq = (const ull*)(Qyc + c * 16);
                #pragma unroll
                for (int j = 0; j < 8; j++) {
                    ull t0 = fma2(X1A, y1[j], fma2(X2A, y2[j], qq[j]));
                    ull t1 = fma2(X1B, y1[j], fma2(X2B, y2[j], qq[j]));
                    float a, b2; upk(t0, a, b2); m0 = fmaxf(m0, fmaxf(a, b2));
                    upk(t1, a, b2); m1 = fmaxf(m1, fmaxf(a, b2));
                }
            }
            sA[w * 64 + lane] = m0;  sA[w * 64 + lane + 32] = m1;
            __syncthreads();
            if (tid < 64) {
                float M = -3e38f;
                #pragma unroll
                for (int i = 0; i < 8; i++) M = fmaxf(M, sA[i * 64 + tid]);
                sRf[tid] = M;
            }
            __syncthreads();
        }
        {
            float R0 = sRf[lane], R1 = sRf[lane + 32];
            ull nR0 = pk(-R0, -R0), nR1 = pk(-R1, -R1);
            float a0 = 0.f, a1 = 0.f, a2 = 0.f, a3 = 0.f;
            for (int c = w; c < nch; c += 8) {
                const ull* y1 = (const ull*)(Y1c + c * 16);
                const ull* y2 = (const ull*)(Y2c + c * 16);
                const ull* qq = (const ull*)(Qyc + c * 16);
                #pragma unroll
                for (int j = 0; j < 8; j++) {
                    ull ly1 = y1[j], ly2 = y2[j], q = qq[j];
                    ull t0 = add2(fma2(X1A, ly1, fma2(X2A, ly2, q)), nR0);
                    ull t1 = add2(fma2(X1B, ly1, fma2(X2B, ly2, q)), nR1);
                    float ta, tb; upk(t0, ta, tb);
                    a0 = fmaf(ex2(fminf(ta, CL)), 1.f, a0);
                    a1 = fmaf(ex2(fminf(tb, CL)), 1.f, a1);
                    upk(t1, ta, tb);
                    a2 = fmaf(ex2(fminf(ta, CL)), 1.f, a2);
                    a3 = fmaf(ex2(fminf(tb, CL)), 1.f, a3);
                }
            }
            sA[w * 64 + lane] = a0 + a1;  sA[w * 64 + lane + 32] = a2 + a3;
        }
        __syncthreads();
        if (tid < 64) {
            float A = 0.f;
            #pragma unroll
            for (int i = 0; i < 8; i++) A += sA[i * 64 + tid];
            A = fmaxf(A, 1e-30f);
            float Lse = sRf[tid] + lg2(A);
            sRf[tid] = Lse;
            g_fs[b * Sn + row0 + tid] = -LOG2S - Lse;    // Qx-form directly
        }
        bat_bar(b, ls);
        {
            const ull* src = (const ull*)(g_fs + b * Sn);
            ull* dst = (ull*)Qx;
            for (int i = tid; i < Sn / 2; i += NT) dst[i] = __ldcg(src + i);
        }
        __syncthreads();

        // ================= g half =================
        if (it == 0) {
            float m = -3e38f;
            int base = w * 128;
            for (int c = 0; c < 16; c++) {
                const ull* x1 = (const ull*)(X1 + (base + c * 8) * 2);
                const ull* x2 = (const ull*)(X2 + (base + c * 8) * 2);
                const ull* qq = (const ull*)(Qx + (base + c * 8) * 2);
                #pragma unroll
                for (int j = 0; j < 8; j++) {
                    ull t = fma2(Y1p, x1[j], fma2(Y2p, x2[j], qq[j]));
                    float a, b2; upk(t, a, b2);
                    m = fmaxf(m, fmaxf(a, b2));
                }
            }
            sA[w * 64 + lane] = m;
            __syncthreads();
            if (tid < 32) {
                float M = -3e38f;
                #pragma unroll
                for (int i = 0; i < 8; i++) M = fmaxf(M, sA[i * 64 + tid]);
                sRg[tid] = M;
            }
            __syncthreads();
        }
        {
            float Rg = sRg[lane];
            ull nR = pk(-Rg, -Rg);
            float a0 = 0.f, a1 = 0.f;
            int base = w * 128;
            for (int c = 0; c < 16; c++) {
                const ull* x1 = (const ull*)(X1 + (base + c * 8) * 2);
                const ull* x2 = (const ull*)(X2 + (base + c * 8) * 2);
                const ull* qq = (const ull*)(Qx + (base + c * 8) * 2);
                #pragma unroll
                for (int j = 0; j < 8; j++) {
                    ull t = add2(fma2(Y1p, x1[j], fma2(Y2p, x2[j], qq[j])), nR);
                    float ta, tb; upk(t, ta, tb);
                    a0 = fmaf(ex2(fminf(ta, CL)), 1.f, a0);
                    a1 = fmaf(ex2(fminf(tb, CL)), 1.f, a1);
                }
            }
            sA[w * 64 + lane] = a0 + a1;
        }
        __syncthreads();
        if (tid < 32) {
            float A = 0.f;
            #pragma unroll
            for (int i = 0; i < 8; i++) A += sA[i * 64 + tid];
            A = fmaxf(A, 1e-30f);
            float Lse = sRg[tid] + lg2(A);
            sRg[tid] = Lse;
            if (tid < myn) g_gs[b * Pn + myc0 + tid] = l2bC[myc0 + tid] - Lse;  // Qy-form
        }
        bat_bar(b, ls);
        for (int i = tid; i < Pv; i += NT) Qyc[i] = __ldcg(&g_gs[b * Pn + i]);
        __syncthreads();
    }

    // ================= final transport distance =================
    {
        float q0 = Qx[fr0], q1 = Qx[fr1];
        float xna = 0.25f * (X1a * X1a + X2a * X2a);
        float xnb = 0.25f * (X1b_ * X1b_ + X2b_ * X2b_);
        float acc = 0.f;
        for (int c = w; c < nch; c += 8) {
            const ull* y1 = (const ull*)(Y1c + c * 16);
            const ull* y2 = (const ull*)(Y2c + c * 16);
            const ull* qq = (const ull*)(Qyc + c * 16);
            #pragma unroll
            for (int j = 0; j < 8; j++) {
                ull ly1 = y1[j], ly2 = y2[j], q = qq[j];
                ull t0 = fma2(X1A, ly1, fma2(X2A, ly2, q));
                ull t1 = fma2(X1B, ly1, fma2(X2B, ly2, q));
                float qa, qb, y1a, y1b, y2a, y2b, t0a, t0b, t1a, t1b;
                upk(q, qa, qb); upk(ly1, y1a, y1b); upk(ly2, y2a, y2b);
                upk(t0, t0a, t0b); upk(t1, t1a, t1b);
                float yna2 = y1a * y1a + y2a * y2a, ynb2 = y1b * y1b + y2b * y2b;
                acc = fmaf(ex2(fminf(t0a + q0, CL)), qa + yna2 + xna - t0a, acc);
                acc = fmaf(ex2(fminf(t0b + q0, CL)), qb + ynb2 + xna - t0b, acc);
                acc = fmaf(ex2(fminf(t1a + q1, CL)), qa + yna2 + xnb - t1a, acc);
                acc = fmaf(ex2(fminf(t1b + q1, CL)), qb + ynb2 + xnb - t1b, acc);
            }
        }
        acc = warp_sum(acc);
        if (lane == 0) sred[w] = acc;
    }
    __syncthreads();
    if (tid == 0) {
        float s = 0.f;
        #pragma unroll
        for (int i = 0; i < 8; i++) s += sred[i];
        g_part[blockIdx.x] = s;
    }

    // ---- grid-wide deterministic reduce ----
    __threadfence();
    __syncthreads();
    if (blockIdx.x == 0) {
        if (tid == 0) {
            atomicAdd(&g_gcnt, 1u);
            while (*((volatile unsigned*)&g_gcnt) < (unsigned)GRID) { }
            __threadfence();
        }
        __syncthreads();
        sA[tid] = __ldcg(&g_part[tid]);
        __syncthreads();
        #pragma unroll
        for (int o = 128; o; o >>= 1) {
            if (tid < o) sA[tid] += sA[tid + o];
            __syncthreads();
        }
        if (tid == 0) {
            out[0] = sA[0] * (1.f / (IL2 * (float)Bn));
            g_gcnt = 0;
        }
    } else {
        if (tid == 0) atomicAdd(&g_gcnt, 1u);
    }
}

extern "C" void kernel_launch(void* const* d_in, const int* in_sizes, int n_in,
                              void* d_out, int out_size) {
    const float* pred   = (const float*)d_in[0];
    const int*   labels = (const int*)d_in[1];
    const float* pos    = (const float*)d_in[2];
    float*       out    = (float*)d_out;

    sinkhorn_kernel<<<GRID, NT>>>(pred, labels, pos, out);
}